// round 3
// baseline (speedup 1.0000x reference)
#include <cuda_runtime.h>
#include <cuda_bf16.h>
#include <cstdint>

#define NTOK 32768
#define EMB  1024
#define NQKV 3072
#define NH   16
#define HD   64

// ---------------- device scratch (no cudaMalloc allowed) ----------------
__device__ __nv_bfloat16 g_h_hi[(size_t)NTOK * EMB];   // 64 MB
__device__ __nv_bfloat16 g_h_lo[(size_t)NTOK * EMB];   // 64 MB
__device__ __nv_bfloat16 g_w_hi[(size_t)NQKV * EMB];   //  6 MB
__device__ __nv_bfloat16 g_w_lo[(size_t)NQKV * EMB];   //  6 MB
__device__ float         g_qkv [(size_t)NTOK * NQKV];  // 384 MB

// ---------------- small PTX helpers (all sm_80-baseline) ----------------
__device__ __forceinline__ uint32_t s2u(const void* p) {
    uint32_t a;
    asm("{ .reg .u64 t; cvta.to.shared.u64 t, %1; cvt.u32.u64 %0, t; }" : "=r"(a) : "l"(p));
    return a;
}

__device__ __forceinline__ void cp16(uint32_t dst, const void* src) {
    asm volatile("cp.async.cg.shared.global [%0], [%1], 16;" :: "r"(dst), "l"(src));
}
#define CP_COMMIT() asm volatile("cp.async.commit_group;" ::: "memory")
#define CP_WAIT1()  asm volatile("cp.async.wait_group 1;" ::: "memory")

__device__ __forceinline__ void ldsm4(uint32_t& r0, uint32_t& r1, uint32_t& r2, uint32_t& r3,
                                      uint32_t addr) {
    asm volatile("ldmatrix.sync.aligned.m8n8.x4.shared.b16 {%0,%1,%2,%3}, [%4];"
                 : "=r"(r0), "=r"(r1), "=r"(r2), "=r"(r3) : "r"(addr));
}

__device__ __forceinline__ void mma16816(float* c, const uint32_t* a, uint32_t b0, uint32_t b1) {
    asm volatile(
        "mma.sync.aligned.m16n8k16.row.col.f32.bf16.bf16.f32 "
        "{%0,%1,%2,%3}, {%4,%5,%6,%7}, {%8,%9}, {%0,%1,%2,%3};"
        : "+f"(c[0]), "+f"(c[1]), "+f"(c[2]), "+f"(c[3])
        : "r"(a[0]), "r"(a[1]), "r"(a[2]), "r"(a[3]), "r"(b0), "r"(b1));
}

// ---------------- fp32 -> bf16 hi/lo split ----------------
__global__ void convert_h_kernel(const float* __restrict__ src) {
    int i4 = blockIdx.x * blockDim.x + threadIdx.x;  // exact cover: 32768*1024 elems / 4
    float4 x = reinterpret_cast<const float4*>(src)[i4];
    __nv_bfloat16 h0 = __float2bfloat16(x.x), h1 = __float2bfloat16(x.y);
    __nv_bfloat16 h2 = __float2bfloat16(x.z), h3 = __float2bfloat16(x.w);
    __nv_bfloat16 l0 = __float2bfloat16(x.x - __bfloat162float(h0));
    __nv_bfloat16 l1 = __float2bfloat16(x.y - __bfloat162float(h1));
    __nv_bfloat16 l2 = __float2bfloat16(x.z - __bfloat162float(h2));
    __nv_bfloat16 l3 = __float2bfloat16(x.w - __bfloat162float(h3));
    reinterpret_cast<ushort4*>(g_h_hi)[i4] = make_ushort4(
        __bfloat16_as_ushort(h0), __bfloat16_as_ushort(h1),
        __bfloat16_as_ushort(h2), __bfloat16_as_ushort(h3));
    reinterpret_cast<ushort4*>(g_h_lo)[i4] = make_ushort4(
        __bfloat16_as_ushort(l0), __bfloat16_as_ushort(l1),
        __bfloat16_as_ushort(l2), __bfloat16_as_ushort(l3));
}

__global__ void convert_w_kernel(const float* __restrict__ src) {
    int i4 = blockIdx.x * blockDim.x + threadIdx.x;  // exact cover: 3072*1024 elems / 4
    float4 x = reinterpret_cast<const float4*>(src)[i4];
    __nv_bfloat16 h0 = __float2bfloat16(x.x), h1 = __float2bfloat16(x.y);
    __nv_bfloat16 h2 = __float2bfloat16(x.z), h3 = __float2bfloat16(x.w);
    __nv_bfloat16 l0 = __float2bfloat16(x.x - __bfloat162float(h0));
    __nv_bfloat16 l1 = __float2bfloat16(x.y - __bfloat162float(h1));
    __nv_bfloat16 l2 = __float2bfloat16(x.z - __bfloat162float(h2));
    __nv_bfloat16 l3 = __float2bfloat16(x.w - __bfloat162float(h3));
    reinterpret_cast<ushort4*>(g_w_hi)[i4] = make_ushort4(
        __bfloat16_as_ushort(h0), __bfloat16_as_ushort(h1),
        __bfloat16_as_ushort(h2), __bfloat16_as_ushort(h3));
    reinterpret_cast<ushort4*>(g_w_lo)[i4] = make_ushort4(
        __bfloat16_as_ushort(l0), __bfloat16_as_ushort(l1),
        __bfloat16_as_ushort(l2), __bfloat16_as_ushort(l3));
}

// ---------------- QKV GEMM: qkv[m,n] = sum_k h[m,k] * W[n,k] + b[n] ----------------
// BM=128, BN=128, BK=32, 3-stage cp.async pipeline, 8 warps (2M x 4N), warp tile 64x32.
// 3 bf16 HMMA products: hi*hi + hi*lo + lo*hi, fp32 accumulate.
#define BM 128
#define BN 128
#define BK 32
#define NT_TILES (NQKV / BN)          // 24
#define SROW 40                       // padded smem row stride in elements (80 B)
#define TILE_B (128 * SROW * 2)       // 10240 B per (matrix, hi/lo)
#define STAGE_B (4 * TILE_B)          // 40960 B: A_hi, A_lo, B_hi, B_lo
#define STAGES 3
#define GEMM_SMEM_BYTES (STAGES * STAGE_B)   // 122880

// offsets within a stage
#define O_AH 0
#define O_AL TILE_B
#define O_BH (2 * TILE_B)
#define O_BL (3 * TILE_B)

__device__ __forceinline__ void load_stage(uint32_t sbase, int tid,
                                           const __nv_bfloat16* gAh, const __nv_bfloat16* gAl,
                                           const __nv_bfloat16* gBh, const __nv_bfloat16* gBl,
                                           int kt) {
    int col0 = kt * BK;
    #pragma unroll
    for (int i = 0; i < 2; i++) {
        int idx = tid + i * 256;
        int r = idx >> 2, c = idx & 3;           // r: 0..127, c: 0..3 (8-elem chunks)
        uint32_t so = (uint32_t)(r * (SROW * 2) + c * 16);
        size_t g = (size_t)r * EMB + col0 + c * 8;
        cp16(sbase + O_AH + so, gAh + g);
        cp16(sbase + O_AL + so, gAl + g);
        cp16(sbase + O_BH + so, gBh + g);
        cp16(sbase + O_BL + so, gBl + g);
    }
}

__global__ __launch_bounds__(256, 1) void qkv_gemm_kernel(const float* __restrict__ bias) {
    extern __shared__ char smem[];
    uint32_t base = s2u(smem);
    int tid = threadIdx.x, wid = tid >> 5, lane = tid & 31;
    int mt_blk = blockIdx.x / NT_TILES, nt_blk = blockIdx.x % NT_TILES;
    int mw = wid & 1, nw = wid >> 1;             // 2 x 4 warp grid

    const __nv_bfloat16* gAh = g_h_hi + (size_t)mt_blk * BM * EMB;
    const __nv_bfloat16* gAl = g_h_lo + (size_t)mt_blk * BM * EMB;
    const __nv_bfloat16* gBh = g_w_hi + (size_t)nt_blk * BN * EMB;
    const __nv_bfloat16* gBl = g_w_lo + (size_t)nt_blk * BN * EMB;

    // ldmatrix lane address components (byte offsets into a tile)
    // A x4: tiles [rows 0-7,k0][rows 8-15,k0][rows 0-7,k0+8][rows 8-15,k0+8]
    int rowA = mw * 64 + (lane & 7) + ((lane >> 3) & 1) * 8;
    int kselA = ((lane >> 4) & 1) * 8;
    // B x4: tiles [n 0-7,k0][n 0-7,k0+8][n 8-15,k0][n 8-15,k0+8]
    int rowB = nw * 32 + (lane & 7) + ((lane >> 4) & 1) * 8;
    int kselB = ((lane >> 3) & 1) * 8;

    float acc[4][4][4];
    #pragma unroll
    for (int i = 0; i < 4; i++)
        #pragma unroll
        for (int j = 0; j < 4; j++)
            #pragma unroll
            for (int q = 0; q < 4; q++) acc[i][j][q] = 0.f;

    // prologue: stages 0,1
    load_stage(base + 0 * STAGE_B, tid, gAh, gAl, gBh, gBl, 0);
    CP_COMMIT();
    load_stage(base + 1 * STAGE_B, tid, gAh, gAl, gBh, gBl, 1);
    CP_COMMIT();

    const int KT = EMB / BK;                     // 32
    for (int kt = 0; kt < KT; kt++) {
        CP_WAIT1();
        __syncthreads();
        uint32_t sb = base + (uint32_t)(kt % STAGES) * STAGE_B;

        uint32_t ah[2][4][4], al[2][4][4], bh[2][2][4], bl[2][2][4];
        #pragma unroll
        for (int ph = 0; ph < 2; ph++) {
            uint32_t ka = (uint32_t)((ph * 16 + kselA) * 2);
            uint32_t kb = (uint32_t)((ph * 16 + kselB) * 2);
            #pragma unroll
            for (int t = 0; t < 4; t++) {
                uint32_t ra = (uint32_t)((rowA + t * 16) * (SROW * 2)) + ka;
                ldsm4(ah[ph][t][0], ah[ph][t][1], ah[ph][t][2], ah[ph][t][3], sb + O_AH + ra);
                ldsm4(al[ph][t][0], al[ph][t][1], al[ph][t][2], al[ph][t][3], sb + O_AL + ra);
            }
            #pragma unroll
            for (int p = 0; p < 2; p++) {
                uint32_t rb = (uint32_t)((rowB + p * 16) * (SROW * 2)) + kb;
                ldsm4(bh[ph][p][0], bh[ph][p][1], bh[ph][p][2], bh[ph][p][3], sb + O_BH + rb);
                ldsm4(bl[ph][p][0], bl[ph][p][1], bl[ph][p][2], bl[ph][p][3], sb + O_BL + rb);
            }
        }
        __syncthreads();                          // all smem reads for this stage done

        if (kt + 2 < KT)
            load_stage(base + (uint32_t)((kt + 2) % STAGES) * STAGE_B, tid,
                       gAh, gAl, gBh, gBl, kt + 2);
        CP_COMMIT();

        #pragma unroll
        for (int ph = 0; ph < 2; ph++) {
            #pragma unroll
            for (int mt = 0; mt < 4; mt++) {
                #pragma unroll
                for (int nt = 0; nt < 4; nt++) {
                    int p = nt >> 1, o = (nt & 1) * 2;
                    mma16816(acc[mt][nt], ah[ph][mt], bh[ph][p][o], bh[ph][p][o + 1]);
                    mma16816(acc[mt][nt], ah[ph][mt], bl[ph][p][o], bl[ph][p][o + 1]);
                    mma16816(acc[mt][nt], al[ph][mt], bh[ph][p][o], bh[ph][p][o + 1]);
                }
            }
        }
    }

    // epilogue: bias add + store fp32
    int gid = lane >> 2, tq = lane & 3;
    #pragma unroll
    for (int mt = 0; mt < 4; mt++) {
        int row = mt_blk * BM + mw * 64 + mt * 16 + gid;
        #pragma unroll
        for (int nt = 0; nt < 4; nt++) {
            int col = nt_blk * BN + nw * 32 + nt * 8 + tq * 2;
            float2 bb = *(const float2*)(bias + col);
            float2 v0 = make_float2(acc[mt][nt][0] + bb.x, acc[mt][nt][1] + bb.y);
            float2 v1 = make_float2(acc[mt][nt][2] + bb.x, acc[mt][nt][3] + bb.y);
            *(float2*)(g_qkv + (size_t)row * NQKV + col) = v0;
            *(float2*)(g_qkv + (size_t)(row + 8) * NQKV + col) = v1;
        }
    }
}

// ---------------- per-token 16x16 head attention + output scatter ----------------
#define ATTN_SMEM (16 * 2048 * 4)

__global__ __launch_bounds__(256, 1) void attn_kernel(float* __restrict__ out) {
    extern __shared__ float sm[];   // [tok][0:1024)=K, [1024:2048)=V
    int tid = threadIdx.x;
    int n0 = blockIdx.x * 16;

    for (int idx = tid; idx < 16 * 512; idx += 256) {
        int tok = idx >> 9, e = idx & 511;
        reinterpret_cast<float4*>(sm)[idx] =
            *(const float4*)(g_qkv + (size_t)(n0 + tok) * NQKV + 1024 + (size_t)e * 4);
    }
    __syncthreads();

    int tok = tid >> 4, i = tid & 15;
    int n = n0 + tok;

    float q[64];
    {
        const float4* qp = (const float4*)(g_qkv + (size_t)n * NQKV + i * HD);
        #pragma unroll
        for (int t = 0; t < 16; t++) {
            float4 v = qp[t];
            q[4 * t + 0] = v.x; q[4 * t + 1] = v.y; q[4 * t + 2] = v.z; q[4 * t + 3] = v.w;
        }
    }
    const float* kp = sm + tok * 2048;
    const float* vp = kp + 1024;

    float s[16];
    #pragma unroll
    for (int j = 0; j < 16; j++) {
        float a = 0.f;
        #pragma unroll
        for (int d = 0; d < 64; d++) a += q[d] * kp[j * 64 + d];
        s[j] = a * 0.03125f;   // 1/sqrt(1024)
    }
    float mx = s[0];
    #pragma unroll
    for (int j = 1; j < 16; j++) mx = fmaxf(mx, s[j]);
    float sum = 0.f;
    #pragma unroll
    for (int j = 0; j < 16; j++) { s[j] = __expf(s[j] - mx); sum += s[j]; }
    float inv = 1.f / sum;

    float o[64];
    #pragma unroll
    for (int d = 0; d < 64; d++) o[d] = 0.f;
    #pragma unroll
    for (int j = 0; j < 16; j++) {
        float p = s[j] * inv;
        #pragma unroll
        for (int d = 0; d < 64; d++) o[d] += p * vp[j * 64 + d];
    }

    // out[i*2048 + n/16, (n%16)*64 + d]
    float4* dst = (float4*)(out + ((size_t)(i * 2048 + (n >> 4))) * 1024 + (n & 15) * 64);
    #pragma unroll
    for (int t = 0; t < 16; t++)
        dst[t] = make_float4(o[4 * t + 0], o[4 * t + 1], o[4 * t + 2], o[4 * t + 3]);
}

// ---------------- launch ----------------
extern "C" void kernel_launch(void* const* d_in, const int* in_sizes, int n_in,
                              void* d_out, int out_size) {
    const float* h = (const float*)d_in[0];
    const float* W = (const float*)d_in[1];
    const float* b = (const float*)d_in[2];
    float* out = (float*)d_out;

    cudaFuncSetAttribute(qkv_gemm_kernel, cudaFuncAttributeMaxDynamicSharedMemorySize, GEMM_SMEM_BYTES);
    cudaFuncSetAttribute(attn_kernel,     cudaFuncAttributeMaxDynamicSharedMemorySize, ATTN_SMEM);

    convert_h_kernel<<<32768, 256>>>(h);
    convert_w_kernel<<<3072, 256>>>(W);
    qkv_gemm_kernel<<<(NTOK / BM) * (NQKV / BN), 256, GEMM_SMEM_BYTES>>>(b);  // 6144 CTAs
    attn_kernel<<<NTOK / 16, 256, ATTN_SMEM>>>(out);
}

// round 5
// speedup vs baseline: 1.1152x; 1.1152x over previous
#include <cuda_runtime.h>
#include <cuda_bf16.h>
#include <cstdint>

#define NTOK 32768
#define EMB  1024
#define NQKV 3072
#define NH   16
#define HD   64

// ---------------- device scratch (no cudaMalloc allowed) ----------------
__device__ __nv_bfloat16 g_h_hi[(size_t)NTOK * EMB];   // 64 MB
__device__ __nv_bfloat16 g_h_lo[(size_t)NTOK * EMB];   // 64 MB
__device__ __nv_bfloat16 g_w_hi[(size_t)NQKV * EMB];   //  6 MB
__device__ __nv_bfloat16 g_w_lo[(size_t)NQKV * EMB];   //  6 MB
__device__ float         g_qkv [(size_t)NTOK * NQKV];  // 384 MB

// ---------------- small PTX helpers (sm_80-baseline only) ----------------
__device__ __forceinline__ uint32_t s2u(const void* p) {
    uint32_t a;
    asm("{ .reg .u64 t; cvta.to.shared.u64 t, %1; cvt.u32.u64 %0, t; }" : "=r"(a) : "l"(p));
    return a;
}

__device__ __forceinline__ void cp16(uint32_t dst, const void* src) {
    asm volatile("cp.async.cg.shared.global [%0], [%1], 16;" :: "r"(dst), "l"(src));
}
#define CP_COMMIT() asm volatile("cp.async.commit_group;" ::: "memory")
#define CP_WAIT0()  asm volatile("cp.async.wait_group 0;" ::: "memory")

__device__ __forceinline__ void ldsm4(uint32_t& r0, uint32_t& r1, uint32_t& r2, uint32_t& r3,
                                      uint32_t addr) {
    asm volatile("ldmatrix.sync.aligned.m8n8.x4.shared.b16 {%0,%1,%2,%3}, [%4];"
                 : "=r"(r0), "=r"(r1), "=r"(r2), "=r"(r3) : "r"(addr));
}

__device__ __forceinline__ void mma16816(float* c, const uint32_t* a, uint32_t b0, uint32_t b1) {
    asm volatile(
        "mma.sync.aligned.m16n8k16.row.col.f32.bf16.bf16.f32 "
        "{%0,%1,%2,%3}, {%4,%5,%6,%7}, {%8,%9}, {%0,%1,%2,%3};"
        : "+f"(c[0]), "+f"(c[1]), "+f"(c[2]), "+f"(c[3])
        : "r"(a[0]), "r"(a[1]), "r"(a[2]), "r"(a[3]), "r"(b0), "r"(b1));
}

// ---------------- fp32 -> bf16 hi/lo split ----------------
__global__ void convert_h_kernel(const float* __restrict__ src) {
    int i4 = blockIdx.x * blockDim.x + threadIdx.x;
    float4 x = reinterpret_cast<const float4*>(src)[i4];
    __nv_bfloat16 h0 = __float2bfloat16(x.x), h1 = __float2bfloat16(x.y);
    __nv_bfloat16 h2 = __float2bfloat16(x.z), h3 = __float2bfloat16(x.w);
    __nv_bfloat16 l0 = __float2bfloat16(x.x - __bfloat162float(h0));
    __nv_bfloat16 l1 = __float2bfloat16(x.y - __bfloat162float(h1));
    __nv_bfloat16 l2 = __float2bfloat16(x.z - __bfloat162float(h2));
    __nv_bfloat16 l3 = __float2bfloat16(x.w - __bfloat162float(h3));
    reinterpret_cast<ushort4*>(g_h_hi)[i4] = make_ushort4(
        __bfloat16_as_ushort(h0), __bfloat16_as_ushort(h1),
        __bfloat16_as_ushort(h2), __bfloat16_as_ushort(h3));
    reinterpret_cast<ushort4*>(g_h_lo)[i4] = make_ushort4(
        __bfloat16_as_ushort(l0), __bfloat16_as_ushort(l1),
        __bfloat16_as_ushort(l2), __bfloat16_as_ushort(l3));
}

__global__ void convert_w_kernel(const float* __restrict__ src) {
    int i4 = blockIdx.x * blockDim.x + threadIdx.x;
    float4 x = reinterpret_cast<const float4*>(src)[i4];
    __nv_bfloat16 h0 = __float2bfloat16(x.x), h1 = __float2bfloat16(x.y);
    __nv_bfloat16 h2 = __float2bfloat16(x.z), h3 = __float2bfloat16(x.w);
    __nv_bfloat16 l0 = __float2bfloat16(x.x - __bfloat162float(h0));
    __nv_bfloat16 l1 = __float2bfloat16(x.y - __bfloat162float(h1));
    __nv_bfloat16 l2 = __float2bfloat16(x.z - __bfloat162float(h2));
    __nv_bfloat16 l3 = __float2bfloat16(x.w - __bfloat162float(h3));
    reinterpret_cast<ushort4*>(g_w_hi)[i4] = make_ushort4(
        __bfloat16_as_ushort(h0), __bfloat16_as_ushort(h1),
        __bfloat16_as_ushort(h2), __bfloat16_as_ushort(h3));
    reinterpret_cast<ushort4*>(g_w_lo)[i4] = make_ushort4(
        __bfloat16_as_ushort(l0), __bfloat16_as_ushort(l1),
        __bfloat16_as_ushort(l2), __bfloat16_as_ushort(l3));
}

// ---------------- QKV GEMM: qkv[m,n] = sum_k h[m,k] * W[n,k] + b[n] ----------------
// BM=128, BN=128, BK=64, 2-stage cp.async double buffer, ONE sync per k-iter.
// 8 warps (2M x 4N), warp tile 64x32. 3 bf16 HMMA products, fp32 accumulate.
#define BM 128
#define BN 128
#define BK 64
#define NT_TILES (NQKV / BN)            // 24
#define SROWB 144                       // padded smem row stride in bytes
#define TILE_B (128 * SROWB)            // 18432 B per (matrix, hi/lo)
#define STAGE_B (4 * TILE_B)            // 73728 B
#define GEMM_SMEM_BYTES (2 * STAGE_B)   // 147456 B

#define O_AH 0
#define O_AL TILE_B
#define O_BH (2 * TILE_B)
#define O_BL (3 * TILE_B)

__device__ __forceinline__ void load_stage(uint32_t sbase, int tid,
                                           const __nv_bfloat16* gAh, const __nv_bfloat16* gAl,
                                           const __nv_bfloat16* gBh, const __nv_bfloat16* gBl,
                                           int kt) {
    int col0 = kt * BK;
    #pragma unroll
    for (int i = 0; i < 4; i++) {
        int idx = tid + i * 256;            // 0..1023
        int r = idx >> 3, c = idx & 7;      // row 0..127, 16B chunk 0..7
        uint32_t so = (uint32_t)(r * SROWB + c * 16);
        size_t g = (size_t)r * EMB + col0 + c * 8;
        cp16(sbase + O_AH + so, gAh + g);
        cp16(sbase + O_AL + so, gAl + g);
        cp16(sbase + O_BH + so, gBh + g);
        cp16(sbase + O_BL + so, gBl + g);
    }
}

__global__ __launch_bounds__(256, 1) void qkv_gemm_kernel(const float* __restrict__ bias) {
    extern __shared__ char smem[];
    uint32_t base = s2u(smem);
    int tid = threadIdx.x, wid = tid >> 5, lane = tid & 31;
    int mt_blk = blockIdx.x / NT_TILES, nt_blk = blockIdx.x % NT_TILES;
    int mw = wid & 1, nw = wid >> 1;        // 2 x 4 warp grid

    const __nv_bfloat16* gAh = g_h_hi + (size_t)mt_blk * BM * EMB;
    const __nv_bfloat16* gAl = g_h_lo + (size_t)mt_blk * BM * EMB;
    const __nv_bfloat16* gBh = g_w_hi + (size_t)nt_blk * BN * EMB;
    const __nv_bfloat16* gBl = g_w_lo + (size_t)nt_blk * BN * EMB;

    int rowA = mw * 64 + (lane & 7) + ((lane >> 3) & 1) * 8;
    int kselA = ((lane >> 4) & 1) * 8;
    int rowB = nw * 32 + (lane & 7) + ((lane >> 4) & 1) * 8;
    int kselB = ((lane >> 3) & 1) * 8;

    float acc[4][4][4];
    #pragma unroll
    for (int i = 0; i < 4; i++)
        #pragma unroll
        for (int j = 0; j < 4; j++)
            #pragma unroll
            for (int q = 0; q < 4; q++) acc[i][j][q] = 0.f;

    load_stage(base, tid, gAh, gAl, gBh, gBl, 0);
    CP_COMMIT();

    const int KT = EMB / BK;                // 16
    for (int kt = 0; kt < KT; kt++) {
        CP_WAIT0();                         // stage kt resident
        __syncthreads();                    // all warps done reading stage kt-1
        uint32_t sb = base + (uint32_t)(kt & 1) * STAGE_B;

        if (kt + 1 < KT) {
            load_stage(base + (uint32_t)((kt + 1) & 1) * STAGE_B, tid,
                       gAh, gAl, gBh, gBl, kt + 1);
            CP_COMMIT();
        }

        #pragma unroll
        for (int ph = 0; ph < 4; ph++) {
            uint32_t ka = (uint32_t)((ph * 16 + kselA) * 2);
            uint32_t kb = (uint32_t)((ph * 16 + kselB) * 2);
            uint32_t ah[4][4], al[4][4], bh[2][4], bl[2][4];
            #pragma unroll
            for (int t = 0; t < 4; t++) {
                uint32_t ra = (uint32_t)((rowA + t * 16) * SROWB) + ka;
                ldsm4(ah[t][0], ah[t][1], ah[t][2], ah[t][3], sb + O_AH + ra);
                ldsm4(al[t][0], al[t][1], al[t][2], al[t][3], sb + O_AL + ra);
            }
            #pragma unroll
            for (int p = 0; p < 2; p++) {
                uint32_t rb = (uint32_t)((rowB + p * 16) * SROWB) + kb;
                ldsm4(bh[p][0], bh[p][1], bh[p][2], bh[p][3], sb + O_BH + rb);
                ldsm4(bl[p][0], bl[p][1], bl[p][2], bl[p][3], sb + O_BL + rb);
            }
            #pragma unroll
            for (int mt = 0; mt < 4; mt++) {
                #pragma unroll
                for (int nt = 0; nt < 4; nt++) {
                    int p = nt >> 1, o = (nt & 1) * 2;
                    mma16816(acc[mt][nt], ah[mt], bh[p][o], bh[p][o + 1]);
                    mma16816(acc[mt][nt], ah[mt], bl[p][o], bl[p][o + 1]);
                    mma16816(acc[mt][nt], al[mt], bh[p][o], bh[p][o + 1]);
                }
            }
        }
    }

    int gid = lane >> 2, tq = lane & 3;
    #pragma unroll
    for (int mt = 0; mt < 4; mt++) {
        int row = mt_blk * BM + mw * 64 + mt * 16 + gid;
        #pragma unroll
        for (int nt = 0; nt < 4; nt++) {
            int col = nt_blk * BN + nw * 32 + nt * 8 + tq * 2;
            float2 bb = *(const float2*)(bias + col);
            float2 v0 = make_float2(acc[mt][nt][0] + bb.x, acc[mt][nt][1] + bb.y);
            float2 v1 = make_float2(acc[mt][nt][2] + bb.x, acc[mt][nt][3] + bb.y);
            *(float2*)(g_qkv + (size_t)row * NQKV + col) = v0;
            *(float2*)(g_qkv + (size_t)(row + 8) * NQKV + col) = v1;
        }
    }
}

// ---------------- per-token 16x16 head attention + output scatter ----------------
// No smem: the 16 head-threads of a token read identical K/V addresses -> L1 broadcast.
__global__ __launch_bounds__(256) void attn_kernel(float* __restrict__ out) {
    int tid = threadIdx.x;
    int n = blockIdx.x * 16 + (tid >> 4);
    int i = tid & 15;

    const float* qkvn = g_qkv + (size_t)n * NQKV;

    float q[64];
    {
        const float4* qp = (const float4*)(qkvn + i * HD);
        #pragma unroll
        for (int t = 0; t < 16; t++) {
            float4 v = qp[t];
            q[4 * t + 0] = v.x; q[4 * t + 1] = v.y; q[4 * t + 2] = v.z; q[4 * t + 3] = v.w;
        }
    }

    const float4* kp = (const float4*)(qkvn + 1024);
    const float4* vp = (const float4*)(qkvn + 2048);

    float s[16];
    #pragma unroll
    for (int j = 0; j < 16; j++) {
        float a = 0.f;
        #pragma unroll
        for (int t = 0; t < 16; t++) {
            float4 kv = kp[j * 16 + t];
            a += q[4 * t + 0] * kv.x + q[4 * t + 1] * kv.y
               + q[4 * t + 2] * kv.z + q[4 * t + 3] * kv.w;
        }
        s[j] = a * 0.03125f;    // 1/sqrt(1024)
    }
    float mx = s[0];
    #pragma unroll
    for (int j = 1; j < 16; j++) mx = fmaxf(mx, s[j]);
    float sum = 0.f;
    #pragma unroll
    for (int j = 0; j < 16; j++) { s[j] = __expf(s[j] - mx); sum += s[j]; }
    float inv = 1.f / sum;

    float o[64];
    #pragma unroll
    for (int d = 0; d < 64; d++) o[d] = 0.f;
    #pragma unroll
    for (int j = 0; j < 16; j++) {
        float p = s[j] * inv;
        #pragma unroll
        for (int t = 0; t < 16; t++) {
            float4 vv = vp[j * 16 + t];
            o[4 * t + 0] += p * vv.x; o[4 * t + 1] += p * vv.y;
            o[4 * t + 2] += p * vv.z; o[4 * t + 3] += p * vv.w;
        }
    }

    float4* dst = (float4*)(out + ((size_t)(i * 2048 + (n >> 4))) * 1024 + (n & 15) * 64);
    #pragma unroll
    for (int t = 0; t < 16; t++)
        dst[t] = make_float4(o[4 * t + 0], o[4 * t + 1], o[4 * t + 2], o[4 * t + 3]);
}

// ---------------- launch ----------------
extern "C" void kernel_launch(void* const* d_in, const int* in_sizes, int n_in,
                              void* d_out, int out_size) {
    const float* h = (const float*)d_in[0];
    const float* W = (const float*)d_in[1];
    const float* b = (const float*)d_in[2];
    float* out = (float*)d_out;

    cudaFuncSetAttribute(qkv_gemm_kernel, cudaFuncAttributeMaxDynamicSharedMemorySize, GEMM_SMEM_BYTES);

    convert_h_kernel<<<32768, 256>>>(h);
    convert_w_kernel<<<3072, 256>>>(W);
    qkv_gemm_kernel<<<(NTOK / BM) * (NQKV / BN), 256, GEMM_SMEM_BYTES>>>(b);  // 6144 CTAs
    attn_kernel<<<NTOK / 16, 256>>>(out);
}